// round 2
// baseline (speedup 1.0000x reference)
#include <cuda_runtime.h>
#include <math.h>
#include <float.h>

#define MROWS   4096
#define NCOLS   16384
#define KHARD   163          // int(0.01 * (16384-1))
#define DELTA_W 5.0f
#define THR0    1.5f
#define THREADS 512
#define FULLM   0xFFFFFFFFu

// per-row partial results (scratch; allocation-free per harness rules)
__device__ float g_partials[MROWS];

__device__ __forceinline__ unsigned fkey(float x) {
    unsigned b = __float_as_uint(x);
    // monotone ascending unsigned key
    return (b & 0x80000000u) ? ~b : (b | 0x80000000u);
}

__device__ __forceinline__ float softplus(float x) {
    // stable: max(x,0) + log1p(exp(-|x|))
    return fmaxf(x, 0.0f) + log1pf(__expf(-fabsf(x)));
}

// Sweep the row from gmem, compact values > thr (excluding index tgt) into cand[].
__device__ __forceinline__ void sweep_candidates(
    const float4* __restrict__ p, int tgt, float thr,
    float* __restrict__ cand, unsigned* s_nc)
{
    const int tid  = threadIdx.x;
    const int lane = tid & 31;
    #pragma unroll
    for (int it = 0; it < NCOLS / 4 / THREADS; ++it) {   // 8 iterations
        int v = it * THREADS + tid;                      // float4 index
        float4 f = p[v];
        int base = v * 4;
        bool p0 = (f.x > thr) && (base + 0 != tgt);
        bool p1 = (f.y > thr) && (base + 1 != tgt);
        bool p2 = (f.z > thr) && (base + 2 != tgt);
        bool p3 = (f.w > thr) && (base + 3 != tgt);
        int cnt = (int)p0 + (int)p1 + (int)p2 + (int)p3;

        // warp inclusive scan of cnt
        int sc = cnt;
        #pragma unroll
        for (int o = 1; o < 32; o <<= 1) {
            int n = __shfl_up_sync(FULLM, sc, o);
            if (lane >= o) sc += n;
        }
        int excl = sc - cnt;
        int wtot = __shfl_sync(FULLM, sc, 31);
        unsigned wbase = 0;
        if (lane == 31) wbase = atomicAdd(s_nc, (unsigned)wtot);
        wbase = __shfl_sync(FULLM, wbase, 31);

        unsigned off = wbase + (unsigned)excl;
        if (p0) cand[off++] = f.x;
        if (p1) cand[off++] = f.y;
        if (p2) cand[off++] = f.z;
        if (p3) cand[off]   = f.w;
    }
}

extern "C" __global__ void __launch_bounds__(THREADS)
mmcl_row_kernel(const float* __restrict__ in, const int* __restrict__ tg)
{
    extern __shared__ float smem_dyn[];
    float*    cand = smem_dyn;                       // up to 16384 floats (64 KB)
    unsigned* hist = (unsigned*)(cand + NCOLS);      // 256 bins (1 KB)

    __shared__ unsigned s_nc, s_prefix, s_r;
    __shared__ unsigned s_suf[256];
    __shared__ float    s_pos, s_warp[THREADS / 32];

    const int tid  = threadIdx.x;
    const int lane = tid & 31;
    const int wid  = tid >> 5;
    const int row  = blockIdx.x;

    const float4* p = (const float4*)(in + (size_t)row * NCOLS);
    const int tgt = tg[row];

    if (tid == 0) {
        s_nc  = 0;
        s_pos = in[(size_t)row * NCOLS + tgt];
    }
    __syncthreads();

    // ---- pass 1: prune to candidates > THR0 ----
    sweep_candidates(p, tgt, THR0, cand, &s_nc);
    __syncthreads();

    bool need_fallback = (s_nc < KHARD);
    __syncthreads();
    if (need_fallback) {                 // fully-correct slow path (won't fire for N(0,1))
        if (tid == 0) s_nc = 0;
        __syncthreads();
        sweep_candidates(p, tgt, -FLT_MAX, cand, &s_nc);
        __syncthreads();
    }

    const unsigned nc = s_nc;

    // ---- 4-level radix select: exact k-th largest key ----
    unsigned prefix = 0;
    unsigned r = KHARD;
    #pragma unroll
    for (int level = 0; level < 4; ++level) {
        const int shift = 24 - 8 * level;
        if (tid < 256) hist[tid] = 0;
        __syncthreads();

        for (unsigned i = tid; i < nc; i += THREADS) {
            unsigned u = fkey(cand[i]);
            // match current prefix (shift+8 can be 32 -> use 64-bit shift)
            if (((unsigned long long)(u ^ prefix) >> (shift + 8)) == 0ULL)
                atomicAdd(&hist[(u >> shift) & 0xFFu], 1u);
        }
        __syncthreads();

        // descending (suffix) inclusive scan over 256 bins
        if (tid < 256) s_suf[tid] = hist[tid];
        __syncthreads();
        #pragma unroll
        for (int off = 1; off < 256; off <<= 1) {
            unsigned v = 0;
            if (tid < 256 && tid + off < 256) v = s_suf[tid + off];
            __syncthreads();
            if (tid < 256) s_suf[tid] += v;
            __syncthreads();
        }

        if (tid < 256) {
            unsigned above = (tid == 255) ? 0u : s_suf[tid + 1];
            if (s_suf[tid] >= r && above < r) {
                s_prefix = prefix | ((unsigned)tid << shift);
                s_r      = r - above;
            }
        }
        __syncthreads();
        prefix = s_prefix;
        r      = s_r;
        __syncthreads();
    }

    const unsigned tkey = prefix;   // exact k-th largest key
    const unsigned rmul = r;        // multiplicity of values == tkey to include

    // ---- sum softplus over strictly-above + tie copies ----
    float sum = 0.0f;
    for (unsigned i = tid; i < nc; i += THREADS) {
        float x = cand[i];
        if (fkey(x) > tkey) sum += softplus(x);
    }
    #pragma unroll
    for (int o = 16; o; o >>= 1) sum += __shfl_down_sync(FULLM, sum, o);
    if (lane == 0) s_warp[wid] = sum;
    __syncthreads();

    if (tid == 0) {
        float tot = 0.0f;
        #pragma unroll
        for (int w = 0; w < THREADS / 32; ++w) tot += s_warp[w];
        float tv = (tkey & 0x80000000u) ? __uint_as_float(tkey ^ 0x80000000u)
                                        : __uint_as_float(~tkey);
        tot += (float)rmul * softplus(tv);
        float pos = s_pos;
        g_partials[row] = DELTA_W * softplus(-pos) + tot / (float)KHARD;
    }
}

extern "C" __global__ void __launch_bounds__(256)
mmcl_reduce_kernel(float* __restrict__ out)
{
    __shared__ float s_warp[8];
    const int tid = threadIdx.x, lane = tid & 31, wid = tid >> 5;
    float s = 0.0f;
    for (int i = tid; i < MROWS; i += 256) s += g_partials[i];
    #pragma unroll
    for (int o = 16; o; o >>= 1) s += __shfl_down_sync(FULLM, s, o);
    if (lane == 0) s_warp[wid] = s;
    __syncthreads();
    if (tid == 0) {
        float tot = 0.0f;
        #pragma unroll
        for (int w = 0; w < 8; ++w) tot += s_warp[w];
        out[0] = tot / (float)MROWS;
    }
}

extern "C" void kernel_launch(void* const* d_in, const int* in_sizes, int n_in,
                              void* d_out, int out_size)
{
    const float* in = (const float*)d_in[0];
    const int*   tg = (const int*)d_in[1];
    float*       out = (float*)d_out;

    const int smem_bytes = NCOLS * (int)sizeof(float) + 256 * (int)sizeof(unsigned); // 66560
    cudaFuncSetAttribute(mmcl_row_kernel,
                         cudaFuncAttributeMaxDynamicSharedMemorySize, smem_bytes);

    mmcl_row_kernel<<<MROWS, THREADS, smem_bytes>>>(in, tg);
    mmcl_reduce_kernel<<<1, 256>>>(out);
}

// round 3
// speedup vs baseline: 1.6206x; 1.6206x over previous
#include <cuda_runtime.h>
#include <math.h>
#include <float.h>

#define MROWS   4096
#define NCOLS   16384
#define KHARD   163          // int(0.01 * (16384-1))
#define DELTA_W 5.0f
#define THR0    1.5f
#define NT      128
#define CAP     2048
#define NBINS0  4096
#define FULLM   0xFFFFFFFFu

__device__ float    g_partials[MROWS];
__device__ unsigned g_done = 0;

__device__ __forceinline__ unsigned fkey(float x) {
    unsigned b = __float_as_uint(x);
    return (b & 0x80000000u) ? ~b : (b | 0x80000000u);   // ascending-monotone key
}
__device__ __forceinline__ float unfkey(unsigned k) {
    return (k & 0x80000000u) ? __uint_as_float(k ^ 0x80000000u) : __uint_as_float(~k);
}
__device__ __forceinline__ float softplus(float x) {
    return fmaxf(x, 0.0f) + log1pf(__expf(-fabsf(x)));
}

// Block-wide "find boundary bin for r-th largest" over hist[0..B).
// Writes s_out = {bin, above(strictly higher count), cnt(bin count)}.
// 2 __syncthreads total.
__device__ __forceinline__ void select_bin(const unsigned* __restrict__ hist, int B,
                                           unsigned r, unsigned* s_warpS,
                                           unsigned* s_out)
{
    const int tid = threadIdx.x, lane = tid & 31, wid = tid >> 5;
    const int P = (B < NT) ? B : NT;
    const int c = B / P;                     // bins per participating thread
    unsigned total = 0;
    if (tid < P) {
        const int base = tid * c;
        for (int j = 0; j < c; ++j) total += hist[base + j];
    }
    // inclusive suffix scan within warp
    unsigned incl = total;
    #pragma unroll
    for (int off = 1; off < 32; off <<= 1) {
        unsigned v = __shfl_down_sync(FULLM, incl, off);
        if (lane + off < 32) incl += v;
    }
    if (lane == 0) s_warpS[wid] = incl;      // warp total (suffix at warp start)
    __syncthreads();
    if (tid < P) {
        unsigned hi = 0;
        #pragma unroll
        for (int w = 0; w < NT / 32; ++w) if (w > wid) hi += s_warpS[w];
        unsigned S = incl + hi;              // inclusive suffix across all threads
        unsigned above_chunk = S - total;    // count in strictly-higher chunks
        if (above_chunk < r && S >= r) {     // boundary lies in my chunk (exactly one thread)
            const int base = tid * c;
            unsigned run = above_chunk;
            for (int j = c - 1; j >= 0; --j) {
                unsigned cnt = hist[base + j];
                if (run + cnt >= r) { s_out[0] = base + j; s_out[1] = run; s_out[2] = cnt; break; }
                run += cnt;
            }
        }
    }
    __syncthreads();
}

extern "C" __global__ void __launch_bounds__(NT)
mmcl_kernel(const float* __restrict__ in, const int* __restrict__ tg,
            float* __restrict__ out)
{
    __shared__ float    cand[CAP];
    __shared__ unsigned hist[NBINS0];
    __shared__ unsigned s_nc;
    __shared__ unsigned s_warpS[NT / 32];
    __shared__ unsigned s_out[3];
    __shared__ float    s_red[NT / 32];
    __shared__ float    s_pos;

    const int tid  = threadIdx.x;
    const int lane = tid & 31;
    const int wid  = tid >> 5;
    const int row  = blockIdx.x;

    const float* __restrict__ rowp = in + (size_t)row * NCOLS;
    const int tgt = tg[row];

    // zero 12-bit histogram (vectorized)
    for (int i = tid; i < NBINS0 / 4; i += NT)
        ((uint4*)hist)[i] = make_uint4(0, 0, 0, 0);
    if (tid == 0) { s_nc = 0; s_pos = rowp[tgt]; }
    __syncthreads();

    // ---- streaming sweep: compact candidates > THR0 (excl. tgt) AND build level-0 hist ----
    const float4* __restrict__ p = (const float4*)rowp;
    #pragma unroll 8
    for (int it = 0; it < NCOLS / 4 / NT; ++it) {        // 32 iterations
        const int v = it * NT + tid;
        float4 f = p[v];
        const int base = v * 4;
        bool p0 = (f.x > THR0) && (base + 0 != tgt);
        bool p1 = (f.y > THR0) && (base + 1 != tgt);
        bool p2 = (f.z > THR0) && (base + 2 != tgt);
        bool p3 = (f.w > THR0) && (base + 3 != tgt);
        unsigned m0 = __ballot_sync(FULLM, p0);
        unsigned m1 = __ballot_sync(FULLM, p1);
        unsigned m2 = __ballot_sync(FULLM, p2);
        unsigned m3 = __ballot_sync(FULLM, p3);
        int c0 = __popc(m0), c1 = __popc(m1), c2 = __popc(m2), c3 = __popc(m3);
        unsigned wbase = 0;
        if (lane == 0) wbase = atomicAdd(&s_nc, (unsigned)(c0 + c1 + c2 + c3));
        wbase = __shfl_sync(FULLM, wbase, 0);
        const unsigned lt = (1u << lane) - 1u;
        unsigned o0 = wbase + __popc(m0 & lt);
        unsigned o1 = wbase + c0 + __popc(m1 & lt);
        unsigned o2 = wbase + c0 + c1 + __popc(m2 & lt);
        unsigned o3 = wbase + c0 + c1 + c2 + __popc(m3 & lt);
        if (p0 && o0 < CAP) { cand[o0] = f.x; atomicAdd(&hist[fkey(f.x) >> 20], 1u); }
        if (p1 && o1 < CAP) { cand[o1] = f.y; atomicAdd(&hist[fkey(f.y) >> 20], 1u); }
        if (p2 && o2 < CAP) { cand[o2] = f.z; atomicAdd(&hist[fkey(f.z) >> 20], 1u); }
        if (p3 && o3 < CAP) { cand[o3] = f.w; atomicAdd(&hist[fkey(f.w) >> 20], 1u); }
    }
    __syncthreads();

    const unsigned nc = s_nc;
    const bool gmode = (nc < KHARD) || (nc > CAP);   // correct-in-principle fallback (never fires for N(0,1))
    if (gmode) {
        // rebuild level-0 hist over the full row from gmem (L2-resident)
        for (int i = tid; i < NBINS0 / 4; i += NT)
            ((uint4*)hist)[i] = make_uint4(0, 0, 0, 0);
        __syncthreads();
        for (int j = tid; j < NCOLS; j += NT)
            if (j != tgt) atomicAdd(&hist[fkey(rowp[j]) >> 20], 1u);
        __syncthreads();
    }

    // ---- hierarchical radix select with early exit: levels of 12,8,8,4 bits ----
    unsigned prefix = 0, r = KHARD, tkey = 0, rmul = 0;
    const int LBITS[4]  = {12, 8, 8, 4};
    const int LSHIFT[4] = {20, 12, 4, 0};
    bool done = false;
    for (int lev = 0; lev < 4 && !done; ++lev) {
        const int shift = LSHIFT[lev];
        const int B = 1 << LBITS[lev];
        if (lev > 0) {
            // rebuild hist for this level over prefix-matching elements
            for (int i = tid; i < B; i += NT) hist[i] = 0;
            __syncthreads();
            const int hibits = shift + LBITS[lev];
            if (!gmode) {
                for (unsigned i = tid; i < nc; i += NT) {
                    unsigned u = fkey(cand[i]);
                    if (((u ^ prefix) >> hibits) == 0u)
                        atomicAdd(&hist[(u >> shift) & (unsigned)(B - 1)], 1u);
                }
            } else {
                for (int j = tid; j < NCOLS; j += NT) {
                    if (j == tgt) continue;
                    unsigned u = fkey(rowp[j]);
                    if (((u ^ prefix) >> hibits) == 0u)
                        atomicAdd(&hist[(u >> shift) & (unsigned)(B - 1)], 1u);
                }
            }
            __syncthreads();
        }
        select_bin(hist, B, r, s_warpS, s_out);
        const unsigned bin = s_out[0], above = s_out[1], cnt = s_out[2];
        prefix |= bin << shift;
        r -= above;
        if (cnt == r && prefix != 0u) {
            // all elements of this bin are included: threshold = "anything >= prefix"
            tkey = prefix - 1u; rmul = 0u; done = true;
        } else if (lev == 3) {
            tkey = prefix; rmul = r; done = true;   // exact key + tie multiplicity
        }
    }

    // ---- sum softplus over selected hard negatives ----
    float sum = 0.0f;
    if (!gmode) {
        for (unsigned i = tid; i < nc; i += NT) {
            float x = cand[i];
            if (fkey(x) > tkey) sum += softplus(x);
        }
    } else {
        for (int j = tid; j < NCOLS; j += NT) {
            if (j == tgt) continue;
            float x = rowp[j];
            if (fkey(x) > tkey) sum += softplus(x);
        }
    }
    #pragma unroll
    for (int o = 16; o; o >>= 1) sum += __shfl_down_sync(FULLM, sum, o);
    if (lane == 0) s_red[wid] = sum;
    __syncthreads();

    if (tid == 0) {
        float tot = 0.0f;
        #pragma unroll
        for (int w = 0; w < NT / 32; ++w) tot += s_red[w];
        tot += (float)rmul * softplus(unfkey(tkey));
        g_partials[row] = DELTA_W * softplus(-s_pos) + tot / (float)KHARD;
        __threadfence();
        unsigned old = atomicAdd(&g_done, 1u);
        s_nc = (old == MROWS - 1) ? 1u : 0u;   // reuse s_nc as "I am last CTA" flag
    }
    __syncthreads();

    if (s_nc) {
        // last CTA reduces all row partials (deterministic order)
        __threadfence();
        float s = 0.0f;
        for (int i = tid; i < MROWS; i += NT) s += __ldcg(&g_partials[i]);
        #pragma unroll
        for (int o = 16; o; o >>= 1) s += __shfl_down_sync(FULLM, s, o);
        if (lane == 0) s_red[wid] = s;
        __syncthreads();
        if (tid == 0) {
            float tot = 0.0f;
            #pragma unroll
            for (int w = 0; w < NT / 32; ++w) tot += s_red[w];
            out[0] = tot / (float)MROWS;
            g_done = 0;                        // reset for next graph replay
        }
    }
}

extern "C" void kernel_launch(void* const* d_in, const int* in_sizes, int n_in,
                              void* d_out, int out_size)
{
    const float* in  = (const float*)d_in[0];
    const int*   tg  = (const int*)d_in[1];
    float*       out = (float*)d_out;
    mmcl_kernel<<<MROWS, NT>>>(in, tg, out);
}

// round 4
// speedup vs baseline: 1.9747x; 1.2185x over previous
#include <cuda_runtime.h>
#include <math.h>
#include <float.h>

#define MROWS   4096
#define NCOLS   16384
#define KHARD   163          // int(0.01 * (16384-1))
#define DELTA_W 5.0f
#define THR0    1.5f
#define NT      128
#define CAP     2048
#define NB      2048         // linear value bins over [THR0, THR0+5)
#define GCAP    128
#define FULLM   0xFFFFFFFFu

__device__ float    g_partials[MROWS];
__device__ unsigned g_done = 0;

__device__ __forceinline__ unsigned fkey(float x) {
    unsigned b = __float_as_uint(x);
    return (b & 0x80000000u) ? ~b : (b | 0x80000000u);
}
__device__ __forceinline__ float unfkey(unsigned k) {
    return (k & 0x80000000u) ? __uint_as_float(k ^ 0x80000000u) : __uint_as_float(~k);
}
__device__ __forceinline__ float softplus(float x) {
    return fmaxf(x, 0.0f) + log1pf(__expf(-fabsf(x)));
}
__device__ __forceinline__ int binof(float x) {          // x > THR0
    int b = (int)((x - THR0) * (float)(NB / 5.0));       // 409.6 per unit
    return b > NB - 1 ? NB - 1 : b;
}

// Block-wide boundary-bin search for the r-th largest over hist[0..B).
// s_out = {bin, count strictly above bin, bin count}. 2 barriers.
__device__ __forceinline__ void select_bin(const unsigned* __restrict__ hist, int B,
                                           unsigned r, unsigned* s_warpS,
                                           unsigned* s_out)
{
    const int tid = threadIdx.x, lane = tid & 31, wid = tid >> 5;
    const int c = B / NT;
    unsigned total = 0;
    const int base = tid * c;
    for (int j = 0; j < c; ++j) total += hist[base + j];
    unsigned incl = total;
    #pragma unroll
    for (int off = 1; off < 32; off <<= 1) {
        unsigned v = __shfl_down_sync(FULLM, incl, off);
        if (lane + off < 32) incl += v;
    }
    if (lane == 0) s_warpS[wid] = incl;
    __syncthreads();
    unsigned hi = 0;
    #pragma unroll
    for (int w = 0; w < NT / 32; ++w) if (w > wid) hi += s_warpS[w];
    unsigned S = incl + hi;
    unsigned above_chunk = S - total;
    if (above_chunk < r && S >= r) {
        unsigned run = above_chunk;
        for (int j = c - 1; j >= 0; --j) {
            unsigned cnt = hist[base + j];
            if (run + cnt >= r) { s_out[0] = base + j; s_out[1] = run; s_out[2] = cnt; break; }
            run += cnt;
        }
    }
    __syncthreads();
}

extern "C" __global__ void __launch_bounds__(NT, 10)
mmcl_kernel(const float* __restrict__ in, const int* __restrict__ tg,
            float* __restrict__ out)
{
    __shared__ float    cand[CAP];
    __shared__ unsigned hist[NB];
    __shared__ unsigned s_nc, s_gn;
    __shared__ unsigned s_warpS[NT / 32];
    __shared__ unsigned s_out[3];
    __shared__ float    s_red[NT / 32];
    __shared__ float    s_gath[GCAP];
    __shared__ float    s_pos, s_tval;
    __shared__ unsigned s_rmul;

    const int tid  = threadIdx.x;
    const int lane = tid & 31;
    const int wid  = tid >> 5;
    const int row  = blockIdx.x;

    const float* __restrict__ rowp = in + (size_t)row * NCOLS;
    const int tgt = tg[row];

    for (int i = tid; i < NB / 4; i += NT)
        ((uint4*)hist)[i] = make_uint4(0, 0, 0, 0);
    if (tid == 0) { s_nc = 0; s_gn = 0; s_pos = rowp[tgt]; }
    __syncthreads();

    // ---- minimal streaming sweep: survivors (incl. positive) -> cand ----
    const float4* __restrict__ p = (const float4*)rowp;
    #pragma unroll 8
    for (int it = 0; it < NCOLS / 4 / NT; ++it) {        // 32 iterations
        float4 f = __ldcs(&p[it * NT + tid]);
        if (f.x > THR0) { unsigned o = atomicAdd(&s_nc, 1u); if (o < CAP) cand[o] = f.x; }
        if (f.y > THR0) { unsigned o = atomicAdd(&s_nc, 1u); if (o < CAP) cand[o] = f.y; }
        if (f.z > THR0) { unsigned o = atomicAdd(&s_nc, 1u); if (o < CAP) cand[o] = f.z; }
        if (f.w > THR0) { unsigned o = atomicAdd(&s_nc, 1u); if (o < CAP) cand[o] = f.w; }
    }
    __syncthreads();

    const unsigned nc  = s_nc;
    const float    pos = s_pos;
    const unsigned pos_in = (pos > THR0) ? 1u : 0u;
    bool gmode = (nc < KHARD + pos_in) || (nc > CAP);

    float tval = 0.0f;
    unsigned rmul = 0;
    bool use_key = false;       // fallback path uses fkey threshold
    unsigned tkey = 0;

    if (!gmode) {
        // histogram over candidates, excluding the positive
        for (unsigned i = tid; i < nc; i += NT)
            atomicAdd(&hist[binof(cand[i])], 1u);
        __syncthreads();
        if (tid == 0 && pos_in) atomicSub(&hist[binof(pos)], 1u);
        __syncthreads();

        select_bin(hist, NB, KHARD, s_warpS, s_out);
        const unsigned bbin = s_out[0], above = s_out[1];
        const unsigned rp = KHARD - above;      // rank within boundary bin

        // gather boundary-bin elements (may include the positive instance)
        for (unsigned i = tid; i < nc; i += NT) {
            float x = cand[i];
            if (binof(x) == (int)bbin) {
                unsigned g = atomicAdd(&s_gn, 1u);
                if (g < GCAP) s_gath[g] = x;
            }
        }
        __syncthreads();

        if (s_gn > GCAP) gmode = true;          // ~impossible; exact fallback below
        else {
            if (tid == 0) {
                int n = (int)s_gn;
                if (pos_in && binof(pos) == (int)bbin) {       // drop one positive instance
                    for (int j = 0; j < n; ++j)
                        if (s_gath[j] == pos) { s_gath[j] = s_gath[n - 1]; --n; break; }
                }
                // partial selection sort: top rp of n
                for (int a = 0; a < (int)rp; ++a) {
                    int mi = a; float mv = s_gath[a];
                    for (int b = a + 1; b < n; ++b)
                        if (s_gath[b] > mv) { mv = s_gath[b]; mi = b; }
                    s_gath[mi] = s_gath[a]; s_gath[a] = mv;
                }
                float tv = s_gath[rp - 1];
                unsigned strict = 0;
                for (int j = 0; j < (int)rp; ++j) if (s_gath[j] > tv) ++strict;
                s_tval = tv; s_rmul = rp - strict;
            }
            __syncthreads();
            tval = s_tval; rmul = s_rmul;
        }
    }

    if (gmode) {
        // exact 3-level fkey radix select from gmem (11,11,10 bits); never fires for N(0,1)
        use_key = true;
        unsigned prefix = 0, r = KHARD;
        const int LSH[3] = {21, 10, 0};
        const int LB[3]  = {2048, 2048, 1024};
        for (int lev = 0; lev < 3; ++lev) {
            const int shift = LSH[lev];
            const int B = LB[lev];
            for (int i = tid; i < B; i += NT) hist[i] = 0;
            __syncthreads();
            for (int j = tid; j < NCOLS; j += NT) {
                if (j == tgt) continue;
                unsigned u = fkey(rowp[j]);
                bool match = (lev == 0) || (((u ^ prefix) >> (shift + (lev == 1 ? 11 : 10))) == 0u);
                if (match) atomicAdd(&hist[(u >> shift) & (unsigned)(B - 1)], 1u);
            }
            __syncthreads();
            select_bin(hist, B, r, s_warpS, s_out);
            prefix |= s_out[0] << shift;
            r -= s_out[1];
            __syncthreads();
        }
        tkey = prefix; rmul = r;
    }

    // ---- sum softplus over hard negatives ----
    float sum = 0.0f;
    if (!use_key) {
        for (unsigned i = tid; i < nc; i += NT) {
            float x = cand[i];
            if (x > tval) sum += softplus(x);
        }
    } else {
        for (int j = tid; j < NCOLS; j += NT) {
            if (j == tgt) continue;
            float x = rowp[j];
            if (fkey(x) > tkey) sum += softplus(x);
        }
    }
    #pragma unroll
    for (int o = 16; o; o >>= 1) sum += __shfl_down_sync(FULLM, sum, o);
    if (lane == 0) s_red[wid] = sum;
    __syncthreads();

    if (tid == 0) {
        float tot = 0.0f;
        #pragma unroll
        for (int w = 0; w < NT / 32; ++w) tot += s_red[w];
        if (!use_key) {
            if (pos > tval) tot -= softplus(pos);     // positive slipped into strict sum
            tot += (float)rmul * softplus(tval);
        } else {
            tot += (float)rmul * softplus(unfkey(tkey));
        }
        g_partials[row] = DELTA_W * softplus(-pos) + tot / (float)KHARD;
        __threadfence();
        unsigned old = atomicAdd(&g_done, 1u);
        s_nc = (old == MROWS - 1) ? 1u : 0u;          // reuse as last-CTA flag
    }
    __syncthreads();

    if (s_nc) {
        __threadfence();
        float s = 0.0f;
        for (int i = tid; i < MROWS; i += NT) s += __ldcg(&g_partials[i]);
        #pragma unroll
        for (int o = 16; o; o >>= 1) s += __shfl_down_sync(FULLM, s, o);
        if (lane == 0) s_red[wid] = s;
        __syncthreads();
        if (tid == 0) {
            float tot = 0.0f;
            #pragma unroll
            for (int w = 0; w < NT / 32; ++w) tot += s_red[w];
            out[0] = tot / (float)MROWS;
            g_done = 0;                               // reset for next graph replay
        }
    }
}

extern "C" void kernel_launch(void* const* d_in, const int* in_sizes, int n_in,
                              void* d_out, int out_size)
{
    const float* in  = (const float*)d_in[0];
    const int*   tg  = (const int*)d_in[1];
    float*       out = (float*)d_out;
    mmcl_kernel<<<MROWS, NT>>>(in, tg, out);
}

// round 5
// speedup vs baseline: 2.1716x; 1.0997x over previous
#include <cuda_runtime.h>
#include <math.h>
#include <float.h>

#define MROWS   4096
#define NCOLS   16384
#define KHARD   163          // int(0.01 * (16384-1))
#define DELTA_W 5.0f
#define THR0    1.5f
#define NT      128
#define NWARP   (NT / 32)
#define SEG     512          // per-warp candidate segment
#define NB      1024         // linear value bins over [THR0, THR0+5)
#define GCAP    128
#define FULLM   0xFFFFFFFFu

__device__ float    g_partials[MROWS];
__device__ unsigned g_done = 0;

__device__ __forceinline__ unsigned fkey(float x) {
    unsigned b = __float_as_uint(x);
    return (b & 0x80000000u) ? ~b : (b | 0x80000000u);
}
__device__ __forceinline__ float unfkey(unsigned k) {
    return (k & 0x80000000u) ? __uint_as_float(k ^ 0x80000000u) : __uint_as_float(~k);
}
__device__ __forceinline__ float softplus(float x) {
    return fmaxf(x, 0.0f) + log1pf(__expf(-fabsf(x)));
}
__device__ __forceinline__ int binof(float x) {          // x > THR0
    int b = (int)((x - THR0) * (float)(NB / 5.0));
    return b > NB - 1 ? NB - 1 : b;
}

// Boundary-bin search for the r-th largest over hist[0..B). Requires B >= NT.
// s_out = {bin, count strictly above bin, bin count}. 2 barriers.
__device__ __forceinline__ void select_bin(const unsigned* __restrict__ hist, int B,
                                           unsigned r, unsigned* s_warpS,
                                           unsigned* s_out)
{
    const int tid = threadIdx.x, lane = tid & 31, wid = tid >> 5;
    const int c = B / NT;
    unsigned total = 0;
    const int base = tid * c;
    for (int j = 0; j < c; ++j) total += hist[base + j];
    unsigned incl = total;
    #pragma unroll
    for (int off = 1; off < 32; off <<= 1) {
        unsigned v = __shfl_down_sync(FULLM, incl, off);
        if (lane + off < 32) incl += v;
    }
    if (lane == 0) s_warpS[wid] = incl;
    __syncthreads();
    unsigned hi = 0;
    #pragma unroll
    for (int w = 0; w < NWARP; ++w) if (w > wid) hi += s_warpS[w];
    unsigned S = incl + hi;
    unsigned above_chunk = S - total;
    if (above_chunk < r && S >= r) {
        unsigned run = above_chunk;
        for (int j = c - 1; j >= 0; --j) {
            unsigned cnt = hist[base + j];
            if (run + cnt >= r) { s_out[0] = base + j; s_out[1] = run; s_out[2] = cnt; break; }
            run += cnt;
        }
    }
    __syncthreads();
}

extern "C" __global__ void __launch_bounds__(NT, 12)
mmcl_kernel(const float* __restrict__ in, const int* __restrict__ tg,
            float* __restrict__ out)
{
    __shared__ float    cand[NWARP * SEG];
    __shared__ unsigned hist[NB];
    __shared__ unsigned s_wn[NWARP];
    __shared__ unsigned s_gn, s_flag;
    __shared__ unsigned s_warpS[NWARP];
    __shared__ unsigned s_out[3];
    __shared__ float    s_red[NWARP];
    __shared__ float    s_gath[GCAP];
    __shared__ float    s_pos, s_tval;
    __shared__ unsigned s_rmul;

    const int tid  = threadIdx.x;
    const int lane = tid & 31;
    const int wid  = tid >> 5;
    const int row  = blockIdx.x;
    const unsigned lt = (1u << lane) - 1u;

    const float* __restrict__ rowp = in + (size_t)row * NCOLS;
    const int tgt = tg[row];

    for (int i = tid; i < NB / 4; i += NT)
        ((uint4*)hist)[i] = make_uint4(0, 0, 0, 0);
    if (tid == 0) { s_gn = 0; s_pos = rowp[tgt]; }

    // ---- atomic-free streaming sweep: ballot-compact into warp-private segments ----
    const float4* __restrict__ p = (const float4*)rowp;
    unsigned cnt = 0;
    const unsigned sbase = wid * SEG;
    #pragma unroll 4
    for (int it = 0; it < NCOLS / 4 / NT; ++it) {        // 32 iterations
        float4 f = __ldcs(&p[it * NT + tid]);
        bool p0 = f.x > THR0, p1 = f.y > THR0, p2 = f.z > THR0, p3 = f.w > THR0;
        unsigned m0 = __ballot_sync(FULLM, p0);
        if (p0) { unsigned o = sbase + cnt + __popc(m0 & lt); if (o < sbase + SEG) cand[o] = f.x; }
        cnt += __popc(m0);
        unsigned m1 = __ballot_sync(FULLM, p1);
        if (p1) { unsigned o = sbase + cnt + __popc(m1 & lt); if (o < sbase + SEG) cand[o] = f.y; }
        cnt += __popc(m1);
        unsigned m2 = __ballot_sync(FULLM, p2);
        if (p2) { unsigned o = sbase + cnt + __popc(m2 & lt); if (o < sbase + SEG) cand[o] = f.z; }
        cnt += __popc(m2);
        unsigned m3 = __ballot_sync(FULLM, p3);
        if (p3) { unsigned o = sbase + cnt + __popc(m3 & lt); if (o < sbase + SEG) cand[o] = f.w; }
        cnt += __popc(m3);
    }
    if (lane == 0) s_wn[wid] = cnt;
    __syncthreads();

    unsigned wn[NWARP];
    unsigned nc = 0; unsigned mx = 0;
    #pragma unroll
    for (int w = 0; w < NWARP; ++w) { wn[w] = s_wn[w]; nc += wn[w]; mx = wn[w] > mx ? wn[w] : mx; }

    const float    pos = s_pos;
    const unsigned pos_in = (pos > THR0) ? 1u : 0u;
    bool gmode = (nc < KHARD + pos_in) || (mx > SEG);

    float tval = 0.0f;
    unsigned rmul = 0;
    bool use_key = false;
    unsigned tkey = 0;

    if (!gmode) {
        // histogram over candidates; thread 0 removes the positive concurrently
        #pragma unroll
        for (int s = 0; s < NWARP; ++s)
            for (unsigned i = tid; i < wn[s]; i += NT)
                atomicAdd(&hist[binof(cand[s * SEG + i])], 1u);
        if (tid == 0 && pos_in) atomicSub(&hist[binof(pos)], 1u);
        __syncthreads();

        select_bin(hist, NB, KHARD, s_warpS, s_out);
        const unsigned bbin = s_out[0], above = s_out[1];
        const unsigned rp = KHARD - above;      // rank within boundary bin

        // gather boundary-bin elements (few; may include the positive instance)
        #pragma unroll
        for (int s = 0; s < NWARP; ++s)
            for (unsigned i = tid; i < wn[s]; i += NT) {
                float x = cand[s * SEG + i];
                if (binof(x) == (int)bbin) {
                    unsigned g = atomicAdd(&s_gn, 1u);
                    if (g < GCAP) s_gath[g] = x;
                }
            }
        __syncthreads();

        if (s_gn > GCAP) gmode = true;          // ~impossible; exact fallback below
        else {
            if (tid == 0) {
                int n = (int)s_gn;
                if (pos_in && binof(pos) == (int)bbin) {   // drop one positive instance
                    for (int j = 0; j < n; ++j)
                        if (s_gath[j] == pos) { s_gath[j] = s_gath[n - 1]; --n; break; }
                }
                for (int a = 0; a < (int)rp; ++a) {        // partial selection sort
                    int mi = a; float mv = s_gath[a];
                    for (int b = a + 1; b < n; ++b)
                        if (s_gath[b] > mv) { mv = s_gath[b]; mi = b; }
                    s_gath[mi] = s_gath[a]; s_gath[a] = mv;
                }
                float tv = s_gath[rp - 1];
                unsigned strict = 0;
                for (int j = 0; j < (int)rp; ++j) if (s_gath[j] > tv) ++strict;
                s_tval = tv; s_rmul = rp - strict;
            }
            __syncthreads();
            tval = s_tval; rmul = s_rmul;
        }
    }

    if (gmode) {
        // exact 4x8-bit fkey radix select from gmem; never fires for N(0,1) inputs
        use_key = true;
        unsigned prefix = 0, r = KHARD;
        for (int lev = 0; lev < 4; ++lev) {
            const int shift = 24 - 8 * lev;
            for (int i = tid; i < 256; i += NT) hist[i] = 0;
            __syncthreads();
            for (int j = tid; j < NCOLS; j += NT) {
                if (j == tgt) continue;
                unsigned u = fkey(rowp[j]);
                bool match = (lev == 0) || (((u ^ prefix) >> (shift + 8)) == 0u);
                if (match) atomicAdd(&hist[(u >> shift) & 255u], 1u);
            }
            __syncthreads();
            select_bin(hist, 256, r, s_warpS, s_out);
            prefix |= s_out[0] << shift;
            r -= s_out[1];
            __syncthreads();
        }
        tkey = prefix; rmul = r;
    }

    // ---- sum softplus over hard negatives ----
    float sum = 0.0f;
    if (!use_key) {
        #pragma unroll
        for (int s = 0; s < NWARP; ++s)
            for (unsigned i = tid; i < wn[s]; i += NT) {
                float x = cand[s * SEG + i];
                if (x > tval) sum += softplus(x);
            }
    } else {
        for (int j = tid; j < NCOLS; j += NT) {
            if (j == tgt) continue;
            float x = rowp[j];
            if (fkey(x) > tkey) sum += softplus(x);
        }
    }
    #pragma unroll
    for (int o = 16; o; o >>= 1) sum += __shfl_down_sync(FULLM, sum, o);
    if (lane == 0) s_red[wid] = sum;
    __syncthreads();

    if (tid == 0) {
        float tot = 0.0f;
        #pragma unroll
        for (int w = 0; w < NWARP; ++w) tot += s_red[w];
        if (!use_key) {
            if (pos > tval) tot -= softplus(pos);     // positive slipped into strict sum
            tot += (float)rmul * softplus(tval);
        } else {
            tot += (float)rmul * softplus(unfkey(tkey));
        }
        g_partials[row] = DELTA_W * softplus(-pos) + tot / (float)KHARD;
        __threadfence();
        unsigned old = atomicAdd(&g_done, 1u);
        s_flag = (old == MROWS - 1) ? 1u : 0u;
    }
    __syncthreads();

    if (s_flag) {
        __threadfence();
        float s = 0.0f;
        for (int i = tid; i < MROWS; i += NT) s += __ldcg(&g_partials[i]);
        #pragma unroll
        for (int o = 16; o; o >>= 1) s += __shfl_down_sync(FULLM, s, o);
        if (lane == 0) s_red[wid] = s;
        __syncthreads();
        if (tid == 0) {
            float tot = 0.0f;
            #pragma unroll
            for (int w = 0; w < NWARP; ++w) tot += s_red[w];
            out[0] = tot / (float)MROWS;
            g_done = 0;                               // reset for next graph replay
        }
    }
}

extern "C" void kernel_launch(void* const* d_in, const int* in_sizes, int n_in,
                              void* d_out, int out_size)
{
    const float* in  = (const float*)d_in[0];
    const int*   tg  = (const int*)d_in[1];
    float*       out = (float*)d_out;
    mmcl_kernel<<<MROWS, NT>>>(in, tg, out);
}

// round 6
// speedup vs baseline: 2.3379x; 1.0766x over previous
#include <cuda_runtime.h>
#include <math.h>
#include <float.h>

#define MROWS   4096
#define NCOLS   16384
#define KHARD   163          // int(0.01 * (16384-1))
#define DELTA_W 5.0f
#define THR0    1.5f
#define NT      128
#define NWARP   (NT / 32)
#define SLOTS   32           // per-thread private candidate slots
#define NB      512          // linear value bins over [THR0, THR0+5)
#define GCAP    64
#define FULLM   0xFFFFFFFFu

__device__ float    g_partials[MROWS];
__device__ unsigned g_done = 0;

__device__ __forceinline__ unsigned fkey(float x) {
    unsigned b = __float_as_uint(x);
    return (b & 0x80000000u) ? ~b : (b | 0x80000000u);
}
__device__ __forceinline__ float unfkey(unsigned k) {
    return (k & 0x80000000u) ? __uint_as_float(k ^ 0x80000000u) : __uint_as_float(~k);
}
__device__ __forceinline__ float softplus(float x) {
    return fmaxf(x, 0.0f) + log1pf(__expf(-fabsf(x)));
}
__device__ __forceinline__ int binof(float x) {          // x > THR0
    int b = (int)((x - THR0) * (float)(NB / 5.0));
    return b > NB - 1 ? NB - 1 : b;
}

// Boundary-bin search for the r-th largest over hist[0..B). Requires B >= NT.
// s_out = {bin, count strictly above bin, bin count}. 2 barriers.
__device__ __forceinline__ void select_bin(const unsigned* __restrict__ hist, int B,
                                           unsigned r, unsigned* s_warpS,
                                           unsigned* s_out)
{
    const int tid = threadIdx.x, lane = tid & 31, wid = tid >> 5;
    const int c = B / NT;
    unsigned total = 0;
    const int base = tid * c;
    for (int j = 0; j < c; ++j) total += hist[base + j];
    unsigned incl = total;
    #pragma unroll
    for (int off = 1; off < 32; off <<= 1) {
        unsigned v = __shfl_down_sync(FULLM, incl, off);
        if (lane + off < 32) incl += v;
    }
    if (lane == 0) s_warpS[wid] = incl;
    __syncthreads();
    unsigned hi = 0;
    #pragma unroll
    for (int w = 0; w < NWARP; ++w) if (w > wid) hi += s_warpS[w];
    unsigned S = incl + hi;
    unsigned above_chunk = S - total;
    if (above_chunk < r && S >= r) {
        unsigned run = above_chunk;
        for (int j = c - 1; j >= 0; --j) {
            unsigned cnt = hist[base + j];
            if (run + cnt >= r) { s_out[0] = base + j; s_out[1] = run; s_out[2] = cnt; break; }
            run += cnt;
        }
    }
    __syncthreads();
}

extern "C" __global__ void __launch_bounds__(NT, 11)
mmcl_kernel(const float* __restrict__ in, const int* __restrict__ tg,
            float* __restrict__ out)
{
    __shared__ float    cand[SLOTS * NT];       // interleaved per-thread segments
    __shared__ unsigned hist[NB];
    __shared__ unsigned s_gn, s_flag;
    __shared__ unsigned s_warpS[NWARP];
    __shared__ unsigned s_out[3];
    __shared__ float    s_red[NWARP];
    __shared__ float    s_gath[GCAP];
    __shared__ float    s_pos, s_bsum;

    const int tid  = threadIdx.x;
    const int lane = tid & 31;
    const int wid  = tid >> 5;
    const int row  = blockIdx.x;

    const float* __restrict__ rowp = in + (size_t)row * NCOLS;
    const int tgt = tg[row];

    for (int i = tid; i < NB / 4; i += NT)
        ((uint4*)hist)[i] = make_uint4(0, 0, 0, 0);
    if (tid == 0) { s_gn = 0; s_pos = rowp[tgt]; }
    __syncthreads();

    // ---- fused sweep: private-slot compaction + histogram, no warp collectives ----
    const float4* __restrict__ p = (const float4*)rowp;
    unsigned mycnt = 0;
    #pragma unroll 8
    for (int it = 0; it < NCOLS / 4 / NT; ++it) {        // 32 iterations
        float4 f = __ldcs(&p[it * NT + tid]);
        if (f.x > THR0) { if (mycnt < SLOTS) cand[mycnt * NT + tid] = f.x; ++mycnt; atomicAdd(&hist[binof(f.x)], 1u); }
        if (f.y > THR0) { if (mycnt < SLOTS) cand[mycnt * NT + tid] = f.y; ++mycnt; atomicAdd(&hist[binof(f.y)], 1u); }
        if (f.z > THR0) { if (mycnt < SLOTS) cand[mycnt * NT + tid] = f.z; ++mycnt; atomicAdd(&hist[binof(f.z)], 1u); }
        if (f.w > THR0) { if (mycnt < SLOTS) cand[mycnt * NT + tid] = f.w; ++mycnt; atomicAdd(&hist[binof(f.w)], 1u); }
    }
    // block totals: nc and overflow
    unsigned t = (mycnt << 8) | (mycnt > SLOTS ? 1u : 0u);
    unsigned red = t;
    #pragma unroll
    for (int o = 16; o; o >>= 1) red += __shfl_down_sync(FULLM, (red & 0xFFFFFF00u), o) | (__shfl_down_sync(FULLM, red, o) & 1u ? 1u : 0u);
    if (lane == 0) s_warpS[wid] = red;
    __syncthreads();
    unsigned nc = 0, ovf = 0;
    #pragma unroll
    for (int w = 0; w < NWARP; ++w) { nc += s_warpS[w] >> 8; ovf |= s_warpS[w] & 1u; }

    const float    pos = s_pos;
    const unsigned pos_in = (pos > THR0) ? 1u : 0u;
    bool gmode = (nc < KHARD + pos_in) || ovf;

    float sum = 0.0f;              // strict-above softplus partial (this thread)
    bool use_key = false;
    unsigned tkey = 0, rmul = 0;

    if (!gmode) {
        if (tid == 0 && pos_in) atomicSub(&hist[binof(pos)], 1u);
        __syncthreads();

        select_bin(hist, NB, KHARD, s_warpS, s_out);
        const int      bbin = (int)s_out[0];
        const unsigned rp   = KHARD - s_out[1];   // rank within boundary bin

        // single fused pass over OWN candidates: strict sum + boundary gather
        const unsigned n_i = mycnt;               // <= SLOTS (no overflow here)
        for (unsigned i = 0; i < n_i; ++i) {
            float x = cand[i * NT + tid];
            int b = binof(x);
            if (b > bbin) sum += softplus(x);
            else if (b == bbin) {
                unsigned g = atomicAdd(&s_gn, 1u);
                if (g < GCAP) s_gath[g] = x;
            }
        }
        __syncthreads();

        if (s_gn > GCAP) { gmode = true; sum = 0.0f; }
        else if (tid == 0) {
            int n = (int)s_gn;
            if (pos_in && binof(pos) == bbin) {   // drop one positive instance
                for (int j = 0; j < n; ++j)
                    if (s_gath[j] == pos) { s_gath[j] = s_gath[n - 1]; --n; break; }
            }
            float bs = 0.0f;                      // top-rp of the boundary bin
            for (int a = 0; a < (int)rp; ++a) {
                int mi = a; float mv = s_gath[a];
                for (int b2 = a + 1; b2 < n; ++b2)
                    if (s_gath[b2] > mv) { mv = s_gath[b2]; mi = b2; }
                s_gath[mi] = s_gath[a]; s_gath[a] = mv;
                bs += softplus(mv);
            }
            s_bsum = bs;
        }
    }

    if (gmode) {
        // exact 4x8-bit fkey radix select from gmem; never fires for N(0,1)
        use_key = true;
        unsigned prefix = 0, r = KHARD;
        for (int lev = 0; lev < 4; ++lev) {
            const int shift = 24 - 8 * lev;
            for (int i = tid; i < 256; i += NT) hist[i] = 0;
            __syncthreads();
            for (int j = tid; j < NCOLS; j += NT) {
                if (j == tgt) continue;
                unsigned u = fkey(rowp[j]);
                bool match = (lev == 0) || (((u ^ prefix) >> (shift + 8)) == 0u);
                if (match) atomicAdd(&hist[(u >> shift) & 255u], 1u);
            }
            __syncthreads();
            select_bin(hist, 256, r, s_warpS, s_out);
            prefix |= s_out[0] << shift;
            r -= s_out[1];
            __syncthreads();
        }
        tkey = prefix; rmul = r;
        for (int j = tid; j < NCOLS; j += NT) {
            if (j == tgt) continue;
            float x = rowp[j];
            if (fkey(x) > tkey) sum += softplus(x);
        }
    }

    // ---- block reduce strict sum ----
    #pragma unroll
    for (int o = 16; o; o >>= 1) sum += __shfl_down_sync(FULLM, sum, o);
    if (lane == 0) s_red[wid] = sum;
    __syncthreads();

    if (tid == 0) {
        float tot = 0.0f;
        #pragma unroll
        for (int w = 0; w < NWARP; ++w) tot += s_red[w];
        if (!use_key) {
            if (pos_in && binof(pos) > (int)s_out[0]) tot -= softplus(pos);  // pos polluted strict sum
            tot += s_bsum;
        } else {
            tot += (float)rmul * softplus(unfkey(tkey));
        }
        g_partials[row] = DELTA_W * softplus(-pos) + tot / (float)KHARD;
        __threadfence();
        unsigned old = atomicAdd(&g_done, 1u);
        s_flag = (old == MROWS - 1) ? 1u : 0u;
    }
    __syncthreads();

    if (s_flag) {
        __threadfence();
        float s = 0.0f;
        for (int i = tid; i < MROWS; i += NT) s += __ldcg(&g_partials[i]);
        #pragma unroll
        for (int o = 16; o; o >>= 1) s += __shfl_down_sync(FULLM, s, o);
        if (lane == 0) s_red[wid] = s;
        __syncthreads();
        if (tid == 0) {
            float tot = 0.0f;
            #pragma unroll
            for (int w = 0; w < NWARP; ++w) tot += s_red[w];
            out[0] = tot / (float)MROWS;
            g_done = 0;                               // reset for next graph replay
        }
    }
}

extern "C" void kernel_launch(void* const* d_in, const int* in_sizes, int n_in,
                              void* d_out, int out_size)
{
    const float* in  = (const float*)d_in[0];
    const int*   tg  = (const int*)d_in[1];
    float*       out = (float*)d_out;
    mmcl_kernel<<<MROWS, NT>>>(in, tg, out);
}

// round 7
// speedup vs baseline: 2.6771x; 1.1451x over previous
#include <cuda_runtime.h>
#include <math.h>
#include <float.h>

#define MROWS   4096
#define NCOLS   16384
#define KHARD   163          // int(0.01 * (16384-1))
#define DELTA_W 5.0f
#define THR0    2.0f
#define NT      128
#define NWARP   (NT / 32)
#define SLOTS   16           // per-thread private candidate slots
#define NB      512          // linear value bins over [THR0, THR0+4)
#define GCAP    64
#define FULLM   0xFFFFFFFFu

__device__ float    g_partials[MROWS];
__device__ unsigned g_done = 0;

__device__ __forceinline__ unsigned fkey(float x) {
    unsigned b = __float_as_uint(x);
    return (b & 0x80000000u) ? ~b : (b | 0x80000000u);
}
__device__ __forceinline__ float unfkey(unsigned k) {
    return (k & 0x80000000u) ? __uint_as_float(k ^ 0x80000000u) : __uint_as_float(~k);
}
__device__ __forceinline__ float softplus(float x) {
    return fmaxf(x, 0.0f) + log1pf(__expf(-fabsf(x)));
}
__device__ __forceinline__ int binof(float x) {          // x > THR0
    int b = (int)((x - THR0) * 128.0f);                  // NB/4 per unit
    return b > NB - 1 ? NB - 1 : b;
}

// Boundary-bin search for the r-th largest over hist[0..B). Requires B >= NT.
// s_out = {bin, count strictly above bin, bin count}. 2 barriers.
__device__ __forceinline__ void select_bin(const unsigned* __restrict__ hist, int B,
                                           unsigned r, unsigned* s_warpS,
                                           unsigned* s_out)
{
    const int tid = threadIdx.x, lane = tid & 31, wid = tid >> 5;
    const int c = B / NT;
    unsigned total = 0;
    const int base = tid * c;
    for (int j = 0; j < c; ++j) total += hist[base + j];
    unsigned incl = total;
    #pragma unroll
    for (int off = 1; off < 32; off <<= 1) {
        unsigned v = __shfl_down_sync(FULLM, incl, off);
        if (lane + off < 32) incl += v;
    }
    if (lane == 0) s_warpS[wid] = incl;
    __syncthreads();
    unsigned hi = 0;
    #pragma unroll
    for (int w = 0; w < NWARP; ++w) if (w > wid) hi += s_warpS[w];
    unsigned S = incl + hi;
    unsigned above_chunk = S - total;
    if (above_chunk < r && S >= r) {
        unsigned run = above_chunk;
        for (int j = c - 1; j >= 0; --j) {
            unsigned cnt = hist[base + j];
            if (run + cnt >= r) { s_out[0] = base + j; s_out[1] = run; s_out[2] = cnt; break; }
            run += cnt;
        }
    }
    __syncthreads();
}

extern "C" __global__ void __launch_bounds__(NT, 12)
mmcl_kernel(const float* __restrict__ in, const int* __restrict__ tg,
            float* __restrict__ out)
{
    __shared__ float    cand[SLOTS * NT];       // interleaved per-thread segments
    __shared__ unsigned hist[NB];
    __shared__ unsigned s_gn, s_flag;
    __shared__ unsigned s_warpS[NWARP];
    __shared__ unsigned s_out[3];
    __shared__ float    s_red[NWARP];
    __shared__ float    s_gath[GCAP];
    __shared__ float    s_pos, s_bsum;
    __shared__ int      s_bbin;

    const int tid  = threadIdx.x;
    const int lane = tid & 31;
    const int wid  = tid >> 5;
    const int row  = blockIdx.x;

    const float* __restrict__ rowp = in + (size_t)row * NCOLS;
    const int tgt = tg[row];

    for (int i = tid; i < NB / 4; i += NT)
        ((uint4*)hist)[i] = make_uint4(0, 0, 0, 0);
    if (tid == 0) { s_gn = 0; s_pos = rowp[tgt]; }

    // ---- minimal sweep: private-slot compaction only (no hist, no collectives) ----
    const float4* __restrict__ p = (const float4*)rowp;
    unsigned mycnt = 0;
    #pragma unroll 8
    for (int it = 0; it < NCOLS / 4 / NT; ++it) {        // 32 iterations
        float4 f = __ldcs(&p[it * NT + tid]);
        if (f.x > THR0) { if (mycnt < SLOTS) cand[mycnt * NT + tid] = f.x; ++mycnt; }
        if (f.y > THR0) { if (mycnt < SLOTS) cand[mycnt * NT + tid] = f.y; ++mycnt; }
        if (f.z > THR0) { if (mycnt < SLOTS) cand[mycnt * NT + tid] = f.z; ++mycnt; }
        if (f.w > THR0) { if (mycnt < SLOTS) cand[mycnt * NT + tid] = f.w; ++mycnt; }
    }
    const unsigned wsum = __reduce_add_sync(FULLM, mycnt);
    const unsigned wovf = __ballot_sync(FULLM, mycnt > SLOTS);
    if (lane == 0) s_warpS[wid] = (wsum << 1) | (wovf ? 1u : 0u);
    __syncthreads();
    unsigned nc = 0, ovf = 0;
    #pragma unroll
    for (int w = 0; w < NWARP; ++w) { nc += s_warpS[w] >> 1; ovf |= s_warpS[w] & 1u; }

    const float    pos = s_pos;
    const unsigned pos_in = (pos > THR0) ? 1u : 0u;
    bool gmode = (nc < KHARD + pos_in) || ovf;

    float sum = 0.0f;              // strict-above softplus partial (this thread)
    bool use_key = false;
    unsigned tkey = 0, rmul = 0;

    if (!gmode) {
        // histogram from own slots (few elements each)
        for (unsigned i = 0; i < mycnt; ++i)
            atomicAdd(&hist[binof(cand[i * NT + tid])], 1u);
        if (tid == 0 && pos_in) atomicSub(&hist[binof(pos)], 1u);
        __syncthreads();

        select_bin(hist, NB, KHARD, s_warpS, s_out);
        const int      bbin = (int)s_out[0];
        const unsigned rp   = KHARD - s_out[1];   // rank within boundary bin
        if (tid == 0) s_bbin = bbin;

        // fused pass over OWN candidates: strict sum + boundary gather
        for (unsigned i = 0; i < mycnt; ++i) {
            float x = cand[i * NT + tid];
            int b = binof(x);
            if (b > bbin) sum += softplus(x);
            else if (b == bbin) {
                unsigned g = atomicAdd(&s_gn, 1u);
                if (g < GCAP) s_gath[g] = x;
            }
        }
        __syncthreads();

        if (s_gn > GCAP) { gmode = true; sum = 0.0f; }
        else if (tid == 0) {
            int n = (int)s_gn;
            if (pos_in && binof(pos) == bbin) {   // drop one positive instance
                for (int j = 0; j < n; ++j)
                    if (s_gath[j] == pos) { s_gath[j] = s_gath[n - 1]; --n; break; }
            }
            float bs = 0.0f;                      // top-rp of the boundary bin
            for (int a = 0; a < (int)rp; ++a) {
                int mi = a; float mv = s_gath[a];
                for (int b2 = a + 1; b2 < n; ++b2)
                    if (s_gath[b2] > mv) { mv = s_gath[b2]; mi = b2; }
                s_gath[mi] = s_gath[a]; s_gath[a] = mv;
                bs += softplus(mv);
            }
            s_bsum = bs;
        }
    }

    if (gmode) {
        // exact 4x8-bit fkey radix select from gmem; never fires for N(0,1)
        use_key = true;
        unsigned prefix = 0, r = KHARD;
        for (int lev = 0; lev < 4; ++lev) {
            const int shift = 24 - 8 * lev;
            for (int i = tid; i < 256; i += NT) hist[i] = 0;
            __syncthreads();
            for (int j = tid; j < NCOLS; j += NT) {
                if (j == tgt) continue;
                unsigned u = fkey(rowp[j]);
                bool match = (lev == 0) || (((u ^ prefix) >> (shift + 8)) == 0u);
                if (match) atomicAdd(&hist[(u >> shift) & 255u], 1u);
            }
            __syncthreads();
            select_bin(hist, 256, r, s_warpS, s_out);
            prefix |= s_out[0] << shift;
            r -= s_out[1];
            __syncthreads();
        }
        tkey = prefix; rmul = r;
        for (int j = tid; j < NCOLS; j += NT) {
            if (j == tgt) continue;
            float x = rowp[j];
            if (fkey(x) > tkey) sum += softplus(x);
        }
    }

    // ---- block reduce strict sum ----
    #pragma unroll
    for (int o = 16; o; o >>= 1) sum += __shfl_down_sync(FULLM, sum, o);
    if (lane == 0) s_red[wid] = sum;
    __syncthreads();

    if (tid == 0) {
        float tot = 0.0f;
        #pragma unroll
        for (int w = 0; w < NWARP; ++w) tot += s_red[w];
        if (!use_key) {
            if (pos_in && binof(pos) > s_bbin) tot -= softplus(pos);  // pos polluted strict sum
            tot += s_bsum;
        } else {
            tot += (float)rmul * softplus(unfkey(tkey));
        }
        g_partials[row] = DELTA_W * softplus(-pos) + tot / (float)KHARD;
        __threadfence();
        unsigned old = atomicAdd(&g_done, 1u);
        s_flag = (old == MROWS - 1) ? 1u : 0u;
    }
    __syncthreads();

    if (s_flag) {
        __threadfence();
        float s = 0.0f;
        for (int i = tid; i < MROWS; i += NT) s += __ldcg(&g_partials[i]);
        #pragma unroll
        for (int o = 16; o; o >>= 1) s += __shfl_down_sync(FULLM, s, o);
        if (lane == 0) s_red[wid] = s;
        __syncthreads();
        if (tid == 0) {
            float tot = 0.0f;
            #pragma unroll
            for (int w = 0; w < NWARP; ++w) tot += s_red[w];
            out[0] = tot / (float)MROWS;
            g_done = 0;                               // reset for next graph replay
        }
    }
}

extern "C" void kernel_launch(void* const* d_in, const int* in_sizes, int n_in,
                              void* d_out, int out_size)
{
    const float* in  = (const float*)d_in[0];
    const int*   tg  = (const int*)d_in[1];
    float*       out = (float*)d_out;
    mmcl_kernel<<<MROWS, NT>>>(in, tg, out);
}